// round 8
// baseline (speedup 1.0000x reference)
#include <cuda_runtime.h>
#include <cuda_bf16.h>

#define NN 2048
#define HH 16
#define FIN 128
#define NBLK 128
#define NTHR 256
#define GSZ (NBLK * NTHR)

// Output layout (float32): node_out [2048*2], edge_out [2048^2], start [2048^2], end [2048^2]
#define OFF_NODE  0
#define OFF_EDGE  4096
#define OFF_START (4096 + 4194304)
#define OFF_END   (4096 + 4194304 + 4194304)

// Scratch (static __device__: zero at load; every launch leaves them re-zeroed
// so CUDA-graph replays are deterministic).
__device__ float g_xw1[NN * HH];
__device__ float g_deg[NN];        // reset in P4
__device__ float g_agg1[NN * HH];  // read+reset in P2
__device__ float g_xw2[NN * 2];
__device__ float g_agg2[NN * 2];   // read+reset in P4
__device__ float g_A[NN * HH];
__device__ float g_Bb[NN * HH];
__device__ unsigned g_bar;         // self-resetting arrive counter
__device__ unsigned g_gen;         // monotonically increasing generation

// ---------------------------------------------------------------------------
// Grid-wide barrier. Valid because NBLK=128 < 148 SMs => all blocks co-resident.
__device__ __forceinline__ void gridbar(unsigned target_gen) {
    __syncthreads();
    if (threadIdx.x == 0) {
        __threadfence();                       // drain my block's writes to L2
        unsigned a = atomicAdd(&g_bar, 1u);
        if (a == NBLK - 1) {
            g_bar = 0;                         // reset for next barrier
            __threadfence();
            atomicAdd(&g_gen, 1u);             // release
        } else {
            while (*(volatile unsigned*)&g_gen < target_gen) { }
        }
    }
    __syncthreads();
}

// Dtype sniff: edge values < 2048 => for int64 all odd 32-bit words are zero.
__device__ __forceinline__ bool is_i64(const void* ei) {
    const uint4* p = (const uint4*)ei;
    uint4 a = __ldg(p), b = __ldg(p + 1);
    return ((a.y | a.w | b.y | b.w) == 0u);
}
__device__ __forceinline__ int edge_at(const void* ei, bool i64, long long idx) {
    if (i64) return (int)__ldg((const long long*)ei + idx);
    return __ldg((const int*)ei + idx);
}

// ---------------------------------------------------------------------------
__global__ void __launch_bounds__(NTHR) k_all(
    const float* __restrict__ x, const void* __restrict__ ei, int E,
    const float* __restrict__ W1, const float* __restrict__ b1,
    const float* __restrict__ W2, const float* __restrict__ b2,
    const float* __restrict__ Wc1, const float* __restrict__ bc1,
    const float* __restrict__ Wc2, const float* __restrict__ bc2,
    float* __restrict__ out)
{
    __shared__ float sW[FIN * HH];   // W1, used in P0
    __shared__ float sWc1[32 * HH];  // Wc1, used in P2 (preloaded here)
    __shared__ float sA[128 * HH];   // A tile, used in P3
    __shared__ unsigned s_gen0;

    int t = threadIdx.x, b = blockIdx.x;
    int gtid = b * NTHR + t;
    if (t == 0) s_gen0 = *(volatile unsigned*)&g_gen;
    for (int idx = t; idx < FIN * HH; idx += NTHR) sW[idx] = W1[idx];
    for (int idx = t; idx < 32 * HH; idx += NTHR) sWc1[idx] = Wc1[idx];
    __syncthreads();
    unsigned gen0 = s_gen0;
    bool i64 = is_i64(ei);

    // ---- P0: xw1 = x@W1 (one output per thread) + degree counting ----
    {
        int row = gtid >> 4, col = gtid & 15;
        const float* xr = x + row * FIN;
        float acc = 0.0f;
#pragma unroll 8
        for (int k = 0; k < FIN; k++) acc = fmaf(xr[k], sW[k * HH + col], acc);
        g_xw1[gtid] = acc;
        for (int e = gtid; e < E; e += GSZ)
            atomicAdd(&g_deg[edge_at(ei, i64, (long long)E + e)], 1.0f);
    }
    gridbar(gen0 + 1);

    // ---- P1: agg1[d] += xw1[s]*dinv[s]  (dinv[d] applied later in P2) ----
    {
        int nitems = E * 4;
        for (int item = gtid; item < nitems; item += GSZ) {
            int e = item >> 2, c0 = (item & 3) * 4;
            int s = edge_at(ei, i64, e);
            int d = edge_at(ei, i64, (long long)E + e);
            float dis = rsqrtf(g_deg[s] + 1.0f);
            float4 xs = *(const float4*)(g_xw1 + s * HH + c0);
            float* ad = g_agg1 + d * HH + c0;
            atomicAdd(ad + 0, xs.x * dis);
            atomicAdd(ad + 1, xs.y * dis);
            atomicAdd(ad + 2, xs.z * dis);
            atomicAdd(ad + 3, xs.w * dis);
        }
    }
    gridbar(gen0 + 2);

    // ---- P2: h = relu(di*agg1 + ds*xw1 + b1); A/Bb/xw2 (warp per node) ----
    {
        int warp = t >> 5, lane = t & 31;
        int o = lane & 15, half = lane >> 4;  // half 0 -> A, 1 -> Bb
        float wreg[HH];
#pragma unroll
        for (int c = 0; c < HH; c++) wreg[c] = sWc1[(half * HH + c) * HH + o];
        float w2reg[HH];
        if (lane < 2) {
#pragma unroll
            for (int c = 0; c < HH; c++) w2reg[c] = __ldg(W2 + c * 2 + lane);
        }
        float b1v = (lane < HH) ? __ldg(b1 + lane) : 0.0f;
        float bc1v = half ? __ldg(bc1 + o) : 0.0f;
        for (int i = b * 8 + warp; i < NN; i += NBLK * 8) {
            float degi = g_deg[i] + 1.0f;
            float di = rsqrtf(degi);
            float ds = di * di;
            float myhv = 0.0f;
            if (lane < HH) {
                float v = di * g_agg1[i * HH + lane] + ds * g_xw1[i * HH + lane] + b1v;
                g_agg1[i * HH + lane] = 0.0f;  // reset for next replay
                myhv = fmaxf(v, 0.0f);
            }
            float acc = bc1v, acc2 = 0.0f;
#pragma unroll
            for (int c = 0; c < HH; c++) {
                float hc = __shfl_sync(0xffffffffu, myhv, c);
                acc = fmaf(hc, wreg[c], acc);
                if (lane < 2) acc2 = fmaf(hc, w2reg[c], acc2);
            }
            if (half == 0) g_A[i * HH + o] = acc;
            else           g_Bb[i * HH + o] = acc;
            if (lane < 2)  g_xw2[i * 2 + lane] = acc2;
        }
    }
    gridbar(gen0 + 3);

    // ---- P3: agg2 slice, then edge MLP + index tile ----
    {
        int nitems = E * 2;
        for (int item = gtid; item < nitems; item += GSZ) {
            int e = item >> 1, c = item & 1;
            int s = edge_at(ei, i64, e);
            int d = edge_at(ei, i64, (long long)E + e);
            float dis = rsqrtf(g_deg[s] + 1.0f);
            atomicAdd(&g_agg2[d * 2 + c], g_xw2[s * 2 + c] * dis);
        }
        // edge tile: bx in [0,8) selects j-range, by in [0,16) selects i-range
        int bx = b & 7, by = b >> 3;
        int j = bx * 256 + t;
        int i0 = by * 128;
        for (int idx = t; idx < 128 * HH; idx += NTHR) sA[idx] = g_A[i0 * HH + idx];
        float4 w[4];
#pragma unroll
        for (int q = 0; q < 4; q++) w[q] = *(const float4*)(Wc2 + q * 4);
        float bb = bc2[0];
        float4 B[4];
#pragma unroll
        for (int q = 0; q < 4; q++) B[q] = *(const float4*)(g_Bb + j * HH + q * 4);
        __syncthreads();
        float fj = (float)j;
        long long base = (long long)i0 * NN + j;
        float* oe = out + OFF_EDGE + base;
        float* os = out + OFF_START + base;
        float* od = out + OFF_END + base;
#pragma unroll 4
        for (int ii = 0; ii < 128; ii++) {
            const float4* a4 = (const float4*)(sA + ii * HH);
            float acc = bb;
#pragma unroll
            for (int q = 0; q < 4; q++) {
                float4 a = a4[q];
                acc = fmaf(fmaxf(a.x + B[q].x, 0.0f), w[q].x, acc);
                acc = fmaf(fmaxf(a.y + B[q].y, 0.0f), w[q].y, acc);
                acc = fmaf(fmaxf(a.z + B[q].z, 0.0f), w[q].z, acc);
                acc = fmaf(fmaxf(a.w + B[q].w, 0.0f), w[q].w, acc);
            }
            float p = __expf(-acc);
            int off = ii * NN;
            oe[off] = __fdividef(1.0f, 1.0f + p);
            os[off] = (float)(i0 + ii);
            od[off] = fj;
        }
    }
    gridbar(gen0 + 4);

    // ---- P4: node_out + scratch resets (blocks 0..15 only) ----
    if (b < 16) {
        int i = b * 128 + (t >> 1);
        int c = t & 1;
        float degi = g_deg[i] + 1.0f;
        float di = rsqrtf(degi);
        float ds = di * di;
        out[OFF_NODE + i * 2 + c] =
            di * g_agg2[i * 2 + c] + ds * g_xw2[i * 2 + c] + __ldg(b2 + c);
        g_agg2[i * 2 + c] = 0.0f;
        if (c == 0) g_deg[i] = 0.0f;
    }
}

// ---------------------------------------------------------------------------
extern "C" void kernel_launch(void* const* d_in, const int* in_sizes, int n_in,
                              void* d_out, int out_size) {
    const float* x   = (const float*)d_in[0];
    const void*  ei  = d_in[1];
    const float* W1  = (const float*)d_in[2];
    const float* b1  = (const float*)d_in[3];
    const float* W2  = (const float*)d_in[4];
    const float* b2  = (const float*)d_in[5];
    const float* Wc1 = (const float*)d_in[6];
    const float* bc1 = (const float*)d_in[7];
    const float* Wc2 = (const float*)d_in[8];
    const float* bc2 = (const float*)d_in[9];
    float* out = (float*)d_out;

    int E = in_sizes[1] / 2;

    k_all<<<NBLK, NTHR>>>(x, ei, E, W1, b1, W2, b2, Wc1, bc1, Wc2, bc2, out);
}

// round 12
// speedup vs baseline: 1.0988x; 1.0988x over previous
#include <cuda_runtime.h>
#include <cuda_bf16.h>

#define NN 2048
#define HH 16
#define FIN 128
#define NBLK 128
#define NTHR 512
#define GSZ (NBLK * NTHR)

// Output layout (float32): node_out [2048*2], edge_out [2048^2], start [2048^2], end [2048^2]
#define OFF_NODE  0
#define OFF_EDGE  4096
#define OFF_START (4096 + 4194304)
#define OFF_END   (4096 + 4194304 + 4194304)

// Scratch (static __device__: zero at load; every launch leaves them re-zeroed
// so CUDA-graph replays are deterministic).
__device__ float g_xw1[NN * HH];
__device__ float g_deg[NN];        // reset in P4
__device__ float g_agg1[NN * HH];  // read+reset in P2
__device__ float g_xw2[NN * 2];
__device__ float g_agg2[NN * 2];   // read+reset in P4
__device__ float g_A[NN * HH];
__device__ float g_Bb[NN * HH];
__device__ unsigned g_bar;         // self-resetting arrive counter
__device__ unsigned g_gen;         // monotonically increasing generation

// ---------------------------------------------------------------------------
// Grid-wide barrier. Valid because NBLK=128 <= 148 SMs => all blocks co-resident.
__device__ __forceinline__ void gridbar(unsigned target_gen) {
    __syncthreads();
    if (threadIdx.x == 0) {
        __threadfence();                       // drain my block's writes to L2
        unsigned a = atomicAdd(&g_bar, 1u);
        if (a == NBLK - 1) {
            g_bar = 0;                         // reset for next barrier
            __threadfence();
            atomicAdd(&g_gen, 1u);             // release
        } else {
            while (*(volatile unsigned*)&g_gen < target_gen) { }
        }
    }
    __syncthreads();
}

// Dtype sniff: edge values < 2048 => for int64 all odd 32-bit words are zero.
__device__ __forceinline__ bool is_i64(const void* ei) {
    const uint4* p = (const uint4*)ei;
    uint4 a = __ldg(p), b = __ldg(p + 1);
    return ((a.y | a.w | b.y | b.w) == 0u);
}
__device__ __forceinline__ int edge_at(const void* ei, bool i64, long long idx) {
    if (i64) return (int)__ldg((const long long*)ei + idx);
    return __ldg((const int*)ei + idx);
}

// ---------------------------------------------------------------------------
__global__ void __launch_bounds__(NTHR) k_all(
    const float* __restrict__ x, const void* __restrict__ ei, int E,
    const float* __restrict__ W1, const float* __restrict__ b1,
    const float* __restrict__ W2, const float* __restrict__ b2,
    const float* __restrict__ Wc1, const float* __restrict__ bc1,
    const float* __restrict__ Wc2, const float* __restrict__ bc2,
    float* __restrict__ out)
{
    __shared__ float sW[FIN * HH];   // W1, used in P0
    __shared__ float sWc1[32 * HH];  // Wc1, used in P2 (preloaded here)
    __shared__ float sA[64 * HH];    // A tile, used in P3
    __shared__ unsigned s_gen0;

    int t = threadIdx.x, b = blockIdx.x;
    int gtid = b * NTHR + t;
    if (t == 0) s_gen0 = *(volatile unsigned*)&g_gen;
    for (int idx = t; idx < FIN * HH; idx += NTHR) sW[idx] = W1[idx];
    for (int idx = t; idx < 32 * HH; idx += NTHR) sWc1[idx] = Wc1[idx];
    __syncthreads();
    unsigned gen0 = s_gen0;
    bool i64 = is_i64(ei);

    // ---- P0: xw1 = x@W1 (threads < 32768: one output each) + degree count ----
    {
        if (gtid < NN * HH) {
            int row = gtid >> 4, col = gtid & 15;
            const float* xr = x + row * FIN;
            float acc = 0.0f;
#pragma unroll 8
            for (int k = 0; k < FIN; k++) acc = fmaf(xr[k], sW[k * HH + col], acc);
            g_xw1[gtid] = acc;
        }
        for (int e = gtid; e < E; e += GSZ)
            atomicAdd(&g_deg[edge_at(ei, i64, (long long)E + e)], 1.0f);
    }
    gridbar(gen0 + 1);

    // ---- P1: agg1[d] += xw1[s]*dinv[s]  (dinv[d] applied later in P2) ----
    {
        int nitems = E * 4;
        for (int item = gtid; item < nitems; item += GSZ) {
            int e = item >> 2, c0 = (item & 3) * 4;
            int s = edge_at(ei, i64, e);
            int d = edge_at(ei, i64, (long long)E + e);
            float dis = rsqrtf(g_deg[s] + 1.0f);
            float4 xs = *(const float4*)(g_xw1 + s * HH + c0);
            float* ad = g_agg1 + d * HH + c0;
            atomicAdd(ad + 0, xs.x * dis);
            atomicAdd(ad + 1, xs.y * dis);
            atomicAdd(ad + 2, xs.z * dis);
            atomicAdd(ad + 3, xs.w * dis);
        }
    }
    gridbar(gen0 + 2);

    // ---- P2: warp per node: h = relu(di*agg1 + ds*xw1 + b1); A/Bb/xw2 ----
    {
        int lane = t & 31;
        int i = gtid >> 5;  // 2048 warps = 2048 nodes, exactly
        int o = lane & 15, half = lane >> 4;  // half 0 -> A, 1 -> Bb
        float wreg[HH];
#pragma unroll
        for (int c = 0; c < HH; c++) wreg[c] = sWc1[(half * HH + c) * HH + o];
        float w2reg[HH];
        if (lane < 2) {
#pragma unroll
            for (int c = 0; c < HH; c++) w2reg[c] = __ldg(W2 + c * 2 + lane);
        }
        float degi = g_deg[i] + 1.0f;
        float di = rsqrtf(degi);
        float ds = di * di;
        float myhv = 0.0f;
        if (lane < HH) {
            float v = di * g_agg1[i * HH + lane] + ds * g_xw1[i * HH + lane] + __ldg(b1 + lane);
            g_agg1[i * HH + lane] = 0.0f;  // reset for next replay
            myhv = fmaxf(v, 0.0f);
        }
        float acc = half ? __ldg(bc1 + o) : 0.0f;
        float acc2 = 0.0f;
#pragma unroll
        for (int c = 0; c < HH; c++) {
            float hc = __shfl_sync(0xffffffffu, myhv, c);
            acc = fmaf(hc, wreg[c], acc);
            if (lane < 2) acc2 = fmaf(hc, w2reg[c], acc2);
        }
        if (half == 0) g_A[i * HH + o] = acc;
        else           g_Bb[i * HH + o] = acc;
        if (lane < 2)  g_xw2[i * 2 + lane] = acc2;
    }
    gridbar(gen0 + 3);

    // ---- P3: agg2 slice, then edge MLP + index tile ----
    {
        int nitems = E * 2;
        for (int item = gtid; item < nitems; item += GSZ) {
            int e = item >> 1, c = item & 1;
            int s = edge_at(ei, i64, e);
            int d = edge_at(ei, i64, (long long)E + e);
            float dis = rsqrtf(g_deg[s] + 1.0f);
            atomicAdd(&g_agg2[d * 2 + c], g_xw2[s * 2 + c] * dis);
        }
        // edge tile: bx in [0,4) selects 512 j's, by in [0,32) selects 64 i's
        int bx = b & 3, by = b >> 2;
        int j = bx * 512 + t;
        int i0 = by * 64;
        for (int idx = t; idx < 64 * HH; idx += NTHR) sA[idx] = g_A[i0 * HH + idx];
        float4 w[4];
#pragma unroll
        for (int q = 0; q < 4; q++) w[q] = *(const float4*)(Wc2 + q * 4);
        float bb = bc2[0];
        float4 B[4];
#pragma unroll
        for (int q = 0; q < 4; q++) B[q] = *(const float4*)(g_Bb + j * HH + q * 4);
        __syncthreads();
        float fj = (float)j;
        long long base = (long long)i0 * NN + j;
        float* oe = out + OFF_EDGE + base;
        float* os = out + OFF_START + base;
        float* od = out + OFF_END + base;
#pragma unroll 4
        for (int ii = 0; ii < 64; ii++) {
            const float4* a4 = (const float4*)(sA + ii * HH);
            float acc = bb;
#pragma unroll
            for (int q = 0; q < 4; q++) {
                float4 a = a4[q];
                acc = fmaf(fmaxf(a.x + B[q].x, 0.0f), w[q].x, acc);
                acc = fmaf(fmaxf(a.y + B[q].y, 0.0f), w[q].y, acc);
                acc = fmaf(fmaxf(a.z + B[q].z, 0.0f), w[q].z, acc);
                acc = fmaf(fmaxf(a.w + B[q].w, 0.0f), w[q].w, acc);
            }
            float p = __expf(-acc);
            int off = ii * NN;
            oe[off] = __fdividef(1.0f, 1.0f + p);
            os[off] = (float)(i0 + ii);
            od[off] = fj;
        }
    }
    gridbar(gen0 + 4);

    // ---- P4: node_out + scratch resets (blocks 0..7, 512 threads each) ----
    if (b < 8) {
        int i = b * 256 + (t >> 1);
        int c = t & 1;
        float degi = g_deg[i] + 1.0f;
        float di = rsqrtf(degi);
        float ds = di * di;
        out[OFF_NODE + i * 2 + c] =
            di * g_agg2[i * 2 + c] + ds * g_xw2[i * 2 + c] + __ldg(b2 + c);
        g_agg2[i * 2 + c] = 0.0f;
        if (c == 0) g_deg[i] = 0.0f;
    }
}

// ---------------------------------------------------------------------------
extern "C" void kernel_launch(void* const* d_in, const int* in_sizes, int n_in,
                              void* d_out, int out_size) {
    const float* x   = (const float*)d_in[0];
    const void*  ei  = d_in[1];
    const float* W1  = (const float*)d_in[2];
    const float* b1  = (const float*)d_in[3];
    const float* W2  = (const float*)d_in[4];
    const float* b2  = (const float*)d_in[5];
    const float* Wc1 = (const float*)d_in[6];
    const float* bc1 = (const float*)d_in[7];
    const float* Wc2 = (const float*)d_in[8];
    const float* bc2 = (const float*)d_in[9];
    float* out = (float*)d_out;

    int E = in_sizes[1] / 2;

    k_all<<<NBLK, NTHR>>>(x, ei, E, W1, b1, W2, b2, Wc1, bc1, Wc2, bc2, out);
}

// round 13
// speedup vs baseline: 1.3696x; 1.2464x over previous
#include <cuda_runtime.h>
#include <cuda_bf16.h>

#define NN 2048
#define HH 16
#define FIN 128
#define NBLK 128
#define NTHR 512
#define GSZ (NBLK * NTHR)

// Output layout (float32): node_out [2048*2], edge_out [2048^2], start [2048^2], end [2048^2]
#define OFF_NODE  0
#define OFF_EDGE  4096
#define OFF_START (4096 + 4194304)
#define OFF_END   (4096 + 4194304 + 4194304)

// Scratch (static __device__: zero at load; every launch leaves them re-zeroed
// so CUDA-graph replays are deterministic).
__device__ float g_xw1[NN * HH];
__device__ float g_deg[NN];        // reset in P4
__device__ float g_agg1[NN * HH];  // read+reset in P2
__device__ float g_xw2[NN * 2];
__device__ float g_agg2[NN * 2];   // read+reset in P4
__device__ float g_A[NN * HH];
__device__ float g_Bb[NN * HH];
__device__ unsigned g_bar;         // self-resetting arrive counter
__device__ unsigned g_gen;         // monotonically increasing generation

// ---------------------------------------------------------------------------
// Grid-wide barrier. Valid because NBLK=128 <= 148 SMs => all blocks co-resident.
__device__ __forceinline__ void gridbar(unsigned target_gen) {
    __syncthreads();
    if (threadIdx.x == 0) {
        __threadfence();
        unsigned a = atomicAdd(&g_bar, 1u);
        if (a == NBLK - 1) {
            g_bar = 0;
            __threadfence();
            atomicAdd(&g_gen, 1u);             // release
        } else {
            while (*(volatile unsigned*)&g_gen < target_gen) { }
        }
    }
    __syncthreads();
}

// Vector reductions (sm_90+): one LTS op for 4 / 2 floats.
__device__ __forceinline__ void red_add_v4(float* p, float a, float b, float c, float d) {
    asm volatile("red.global.add.v4.f32 [%0], {%1, %2, %3, %4};"
                 :: "l"(p), "f"(a), "f"(b), "f"(c), "f"(d) : "memory");
}
__device__ __forceinline__ void red_add_v2(float* p, float a, float b) {
    asm volatile("red.global.add.v2.f32 [%0], {%1, %2};"
                 :: "l"(p), "f"(a), "f"(b) : "memory");
}

// Dtype sniff: edge values < 2048 => for int64 all odd 32-bit words are zero.
__device__ __forceinline__ bool is_i64(const void* ei) {
    const uint4* p = (const uint4*)ei;
    uint4 a = __ldg(p), b = __ldg(p + 1);
    return ((a.y | a.w | b.y | b.w) == 0u);
}
__device__ __forceinline__ int edge_at(const void* ei, bool i64, long long idx) {
    if (i64) return (int)__ldg((const long long*)ei + idx);
    return __ldg((const int*)ei + idx);
}

// ---------------------------------------------------------------------------
__global__ void __launch_bounds__(NTHR) k_all(
    const float* __restrict__ x, const void* __restrict__ ei, int E,
    const float* __restrict__ W1, const float* __restrict__ b1,
    const float* __restrict__ W2, const float* __restrict__ b2,
    const float* __restrict__ Wc1, const float* __restrict__ bc1,
    const float* __restrict__ Wc2, const float* __restrict__ bc2,
    float* __restrict__ out)
{
    __shared__ float sW[FIN * HH];   // W1 (P0, blocks < 64)
    __shared__ float sWc1[32 * HH];  // Wc1 (P2)
    __shared__ float sA[32 * HH];    // A tile (P3)
    __shared__ unsigned s_gen0;

    int t = threadIdx.x, b = blockIdx.x;
    int gtid = b * NTHR + t;
    if (t == 0) s_gen0 = *(volatile unsigned*)&g_gen;
    if (b < 64)
        for (int idx = t; idx < FIN * HH; idx += NTHR) sW[idx] = W1[idx];
    for (int idx = t; idx < 32 * HH; idx += NTHR) sWc1[idx] = Wc1[idx];
    __syncthreads();
    unsigned gen0 = s_gen0;
    bool i64 = is_i64(ei);

    // ---- P0: blocks 0-63: xw1 = x@W1 (one output/thread, float4 x loads);
    //          blocks 64-127: degree counting (2 edges/thread, vector loads) ----
    if (b < 64) {
        int row = gtid >> 4, col = gtid & 15;
        const float4* xr4 = (const float4*)(x + row * FIN);
        float acc = 0.0f;
#pragma unroll
        for (int k4 = 0; k4 < FIN / 4; k4++) {
            float4 xv = __ldg(xr4 + k4);
            acc = fmaf(xv.x, sW[(k4 * 4 + 0) * HH + col], acc);
            acc = fmaf(xv.y, sW[(k4 * 4 + 1) * HH + col], acc);
            acc = fmaf(xv.z, sW[(k4 * 4 + 2) * HH + col], acc);
            acc = fmaf(xv.w, sW[(k4 * 4 + 3) * HH + col], acc);
        }
        g_xw1[gtid] = acc;
    } else {
        int g = (b - 64) * NTHR + t;          // [0, 32768)
        int e0 = g * 2;
        if (e0 < E) {
            int d0, d1;
            if (i64) {
                longlong2 v = __ldg((const longlong2*)((const long long*)ei + E + e0));
                d0 = (int)v.x; d1 = (int)v.y;
            } else {
                int2 v = __ldg((const int2*)((const int*)ei + E + e0));
                d0 = v.x; d1 = v.y;
            }
            atomicAdd(&g_deg[d0], 1.0f);
            if (e0 + 1 < E) atomicAdd(&g_deg[d1], 1.0f);
        }
    }
    gridbar(gen0 + 1);

    // ---- P1: thread-per-edge: agg1[d] += xw1[s]*dinv[s] via red.v4 ----
    for (int e = gtid; e < E; e += GSZ) {
        int s = edge_at(ei, i64, e);
        int d = edge_at(ei, i64, (long long)E + e);
        float dis = rsqrtf(g_deg[s] + 1.0f);
        const float4* xs = (const float4*)(g_xw1 + s * HH);
        float* ad = g_agg1 + d * HH;
#pragma unroll
        for (int q = 0; q < 4; q++) {
            float4 v = __ldg(xs + q);
            red_add_v4(ad + q * 4, v.x * dis, v.y * dis, v.z * dis, v.w * dis);
        }
    }
    gridbar(gen0 + 2);

    // ---- P2: warp-per-node: h = relu(di*agg1 + ds*xw1 + b1); A/Bb/xw2 ----
    {
        int lane = t & 31;
        int i = gtid >> 5;  // 2048 warps = 2048 nodes
        int o = lane & 15, half = lane >> 4;  // 0 -> A, 1 -> Bb
        float wreg[HH];
#pragma unroll
        for (int c = 0; c < HH; c++) wreg[c] = sWc1[(half * HH + c) * HH + o];
        float w2reg[HH];
        if (lane < 2) {
#pragma unroll
            for (int c = 0; c < HH; c++) w2reg[c] = __ldg(W2 + c * 2 + lane);
        }
        float degi = g_deg[i] + 1.0f;
        float di = rsqrtf(degi);
        float ds = di * di;
        float myhv = 0.0f;
        if (lane < HH) {
            float v = di * g_agg1[i * HH + lane] + ds * g_xw1[i * HH + lane] + __ldg(b1 + lane);
            g_agg1[i * HH + lane] = 0.0f;  // reset for next replay
            myhv = fmaxf(v, 0.0f);
        }
        float acc = half ? __ldg(bc1 + o) : 0.0f;
        float acc2 = 0.0f;
#pragma unroll
        for (int c = 0; c < HH; c++) {
            float hc = __shfl_sync(0xffffffffu, myhv, c);
            acc = fmaf(hc, wreg[c], acc);
            if (lane < 2) acc2 = fmaf(hc, w2reg[c], acc2);
        }
        if (half == 0) g_A[i * HH + o] = acc;
        else           g_Bb[i * HH + o] = acc;
        if (lane < 2)  g_xw2[i * 2 + lane] = acc2;
    }
    gridbar(gen0 + 3);

    // ---- P3: agg2 (thread-per-edge, red.v2), then edge MLP + index tile ----
    {
        for (int e = gtid; e < E; e += GSZ) {
            int s = edge_at(ei, i64, e);
            int d = edge_at(ei, i64, (long long)E + e);
            float dis = rsqrtf(g_deg[s] + 1.0f);
            float2 xv = *(const float2*)(g_xw2 + s * 2);
            red_add_v2(g_agg2 + d * 2, xv.x * dis, xv.y * dis);
        }
        // edge tile: bx in {0,1} selects 1024 j's (2 per thread), by in [0,64) selects 32 i's
        int bx = b & 1, by = b >> 1;
        int j0 = bx * 1024 + t * 2;
        int i0 = by * 32;
        sA[t] = g_A[i0 * HH + t];  // 512 floats = 32 rows x 16
        float4 w[4];
#pragma unroll
        for (int q = 0; q < 4; q++) w[q] = *(const float4*)(Wc2 + q * 4);
        float bb = bc2[0];
        float4 B0[4], B1[4];
#pragma unroll
        for (int q = 0; q < 4; q++) {
            B0[q] = *(const float4*)(g_Bb + j0 * HH + q * 4);
            B1[q] = *(const float4*)(g_Bb + (j0 + 1) * HH + q * 4);
        }
        __syncthreads();
        float2 fj = make_float2((float)j0, (float)(j0 + 1));
        long long base = (long long)i0 * NN + j0;
        float2* oe = (float2*)(out + OFF_EDGE + base);
        float2* os = (float2*)(out + OFF_START + base);
        float2* od = (float2*)(out + OFF_END + base);
#pragma unroll 4
        for (int ii = 0; ii < 32; ii++) {
            const float4* a4 = (const float4*)(sA + ii * HH);
            float acc0 = bb, acc1 = bb;
#pragma unroll
            for (int q = 0; q < 4; q++) {
                float4 a = a4[q];
                acc0 = fmaf(fmaxf(a.x + B0[q].x, 0.0f), w[q].x, acc0);
                acc0 = fmaf(fmaxf(a.y + B0[q].y, 0.0f), w[q].y, acc0);
                acc0 = fmaf(fmaxf(a.z + B0[q].z, 0.0f), w[q].z, acc0);
                acc0 = fmaf(fmaxf(a.w + B0[q].w, 0.0f), w[q].w, acc0);
                acc1 = fmaf(fmaxf(a.x + B1[q].x, 0.0f), w[q].x, acc1);
                acc1 = fmaf(fmaxf(a.y + B1[q].y, 0.0f), w[q].y, acc1);
                acc1 = fmaf(fmaxf(a.z + B1[q].z, 0.0f), w[q].z, acc1);
                acc1 = fmaf(fmaxf(a.w + B1[q].w, 0.0f), w[q].w, acc1);
            }
            float p0 = __expf(-acc0), p1 = __expf(-acc1);
            int off = ii * (NN / 2);
            oe[off] = make_float2(__fdividef(1.0f, 1.0f + p0),
                                  __fdividef(1.0f, 1.0f + p1));
            float fi = (float)(i0 + ii);
            os[off] = make_float2(fi, fi);
            od[off] = fj;
        }
    }
    gridbar(gen0 + 4);

    // ---- P4: node_out + scratch resets (blocks 0..7, 512 threads each) ----
    if (b < 8) {
        int i = b * 256 + (t >> 1);
        int c = t & 1;
        float degi = g_deg[i] + 1.0f;
        float di = rsqrtf(degi);
        float ds = di * di;
        out[OFF_NODE + i * 2 + c] =
            di * g_agg2[i * 2 + c] + ds * g_xw2[i * 2 + c] + __ldg(b2 + c);
        g_agg2[i * 2 + c] = 0.0f;
        if (c == 0) g_deg[i] = 0.0f;
    }
}

// ---------------------------------------------------------------------------
extern "C" void kernel_launch(void* const* d_in, const int* in_sizes, int n_in,
                              void* d_out, int out_size) {
    const float* x   = (const float*)d_in[0];
    const void*  ei  = d_in[1];
    const float* W1  = (const float*)d_in[2];
    const float* b1  = (const float*)d_in[3];
    const float* W2  = (const float*)d_in[4];
    const float* b2  = (const float*)d_in[5];
    const float* Wc1 = (const float*)d_in[6];
    const float* bc1 = (const float*)d_in[7];
    const float* Wc2 = (const float*)d_in[8];
    const float* bc2 = (const float*)d_in[9];
    float* out = (float*)d_out;

    int E = in_sizes[1] / 2;

    k_all<<<NBLK, NTHR>>>(x, ei, E, W1, b1, W2, b2, Wc1, bc1, Wc2, bc2, out);
}